// round 3
// baseline (speedup 1.0000x reference)
#include <cuda_runtime.h>
#include <cuda_fp16.h>
#include <cstdint>

// ============================================================================
// Problem: B=4, Lq=Lk=4096, D=512, fp32. Output = (context, attn) concatenated.
// ============================================================================
#define BATCH 4
#define LSEQ  4096
#define DDIM  512
#define NELEM (BATCH * LSEQ * DDIM)              // 8,388,608
#define CTX_ELEMS ((size_t)BATCH * LSEQ * DDIM)

// fp16 hi/lo split scratch (device globals: sanctioned allocation-free scratch)
__device__ __align__(16) __half g_Qh[NELEM];
__device__ __align__(16) __half g_Ql[NELEM];
__device__ __align__(16) __half g_Vh[NELEM];
__device__ __align__(16) __half g_Vl[NELEM];
__device__ __align__(16) __half g_VTh[NELEM];  // [B, D, Lk]
__device__ __align__(16) __half g_VTl[NELEM];

// ============================================================================
// Helpers
// ============================================================================
__device__ __forceinline__ uint32_t smem_to_u32(const void* smem_ptr) {
    uint32_t addr;
    asm("{ .reg .u64 tmp; cvta.to.shared.u64 tmp, %1; cvt.u32.u64 %0, tmp; }"
        : "=r"(addr) : "l"(smem_ptr));
    return addr;
}

// ldmatrix x4 (non-transposed) from shared memory
__device__ __forceinline__ void ldsm_x4(uint32_t (&r)[4], uint32_t addr) {
    asm volatile("ldmatrix.sync.aligned.m8n8.x4.shared.b16 {%0,%1,%2,%3}, [%4];"
                 : "=r"(r[0]), "=r"(r[1]), "=r"(r[2]), "=r"(r[3]) : "r"(addr));
}

// mma m16n8k16 row.col fp16 x fp16 -> fp32 accumulate
__device__ __forceinline__ void mma16816(float (&d)[4], const uint32_t (&a)[4],
                                         uint32_t b0, uint32_t b1) {
    asm volatile(
        "mma.sync.aligned.m16n8k16.row.col.f32.f16.f16.f32 "
        "{%0,%1,%2,%3}, {%4,%5,%6,%7}, {%8,%9}, {%0,%1,%2,%3};"
        : "+f"(d[0]), "+f"(d[1]), "+f"(d[2]), "+f"(d[3])
        : "r"(a[0]), "r"(a[1]), "r"(a[2]), "r"(a[3]), "r"(b0), "r"(b1));
}

// SW128 swizzle for 128B rows: byte_off ^ ((byte_off>>3)&0x70)
__device__ __forceinline__ uint32_t sw128(uint32_t off) {
    return off ^ ((off >> 3) & 0x70);
}

// smem tile offsets (relative to 1024-aligned tile base). Tiles are 128 rows x
// 64 halfs (128B rows) = 16 KB each.
#define OFF_AH 0
#define OFF_AL 16384
#define OFF_BH 32768
#define OFF_BL 49152
#define SMEM_DYN (65536 + 1024)

// ============================================================================
// P0a: elementwise convert Q,V -> fp16 hi/lo
// ============================================================================
__global__ void convert_qv(const float* __restrict__ Q, const float* __restrict__ V) {
    size_t i = (size_t)blockIdx.x * 256 + threadIdx.x;
    float q = Q[i];
    __half qh = __float2half_rn(q);
    g_Qh[i] = qh;
    g_Ql[i] = __float2half_rn(q - __half2float(qh));
    float v = V[i];
    __half vh = __float2half_rn(v);
    g_Vh[i] = vh;
    g_Vl[i] = __float2half_rn(v - __half2float(vh));
}

// ============================================================================
// P0b: transpose+convert V -> VT[b][d][k] fp16 hi/lo
// ============================================================================
__global__ void transpose_conv(const float* __restrict__ V) {
    __shared__ float tile[32][33];
    int b = blockIdx.z;
    int k0 = blockIdx.x * 32, d0 = blockIdx.y * 32;
    int tx = threadIdx.x, ty = threadIdx.y;  // 32 x 8
#pragma unroll
    for (int j = 0; j < 4; j++) {
        tile[ty + 8 * j][tx] =
            V[((size_t)b * LSEQ + k0 + ty + 8 * j) * DDIM + d0 + tx];
    }
    __syncthreads();
#pragma unroll
    for (int j = 0; j < 4; j++) {
        int d = d0 + ty + 8 * j, k = k0 + tx;
        float v = tile[tx][ty + 8 * j];
        size_t o = ((size_t)b * DDIM + d) * LSEQ + k;
        __half h = __float2half_rn(v);
        g_VTh[o] = h;
        g_VTl[o] = __float2half_rn(v - __half2float(h));
    }
}

// ============================================================================
// Tile loader: 128 rows x 64 halfs (16B vectors), SW128 swizzled, 256 threads
// ============================================================================
__device__ __forceinline__ void load_tile_h(char* tbp, int off,
                                            const __half* __restrict__ gsrc,
                                            int rowStrideU4, int chunk, int tid) {
    const uint4* g = reinterpret_cast<const uint4*>(gsrc);
#pragma unroll
    for (int it = 0; it < 4; it++) {
        int idx = tid + 256 * it;          // 0..1023
        int r = idx >> 3, s = idx & 7;
        uint4 val = g[(size_t)r * rowStrideU4 + (size_t)chunk * 8 + s];
        uint32_t sw = sw128((uint32_t)(r * 128 + s * 16));
        *reinterpret_cast<uint4*>(tbp + off + sw) = val;
    }
}

// ============================================================================
// Warp MMA core: fragments + 3-product accumulate for one k16 step.
// acc[2][8][4], warp tile 32(m) x 64(n). tA/tB are smem u32 of hi tiles;
// lo tiles are at +16384.
// ============================================================================
struct Frag {
    uint32_t ah[2][4], al[2][4];
    uint32_t bh[4][4], bl[4][4];
};

__device__ __forceinline__ void load_frags(Frag& f, uint32_t tA, uint32_t tB,
                                           int mw, int nw, int kk, int lane) {
    int kb = kk * 32 + ((lane >> 4) << 4);
#pragma unroll
    for (int mb = 0; mb < 2; mb++) {
        int row = mw * 32 + mb * 16 + (lane & 15);
        uint32_t addr = tA + row * 128 + (kb ^ ((row & 7) << 4));
        ldsm_x4(f.ah[mb], addr);
        ldsm_x4(f.al[mb], addr + 16384);
    }
#pragma unroll
    for (int p = 0; p < 4; p++) {
        int row = nw * 64 + p * 16 + ((lane >> 3 & 1) << 3) + (lane & 7);
        uint32_t addr = tB + row * 128 + (kb ^ ((row & 7) << 4));
        ldsm_x4(f.bh[p], addr);
        ldsm_x4(f.bl[p], addr + 16384);
    }
}

__device__ __forceinline__ void mma_3prod(float (&acc)[2][8][4], const Frag& f) {
#pragma unroll
    for (int mb = 0; mb < 2; mb++)
#pragma unroll
        for (int nb = 0; nb < 8; nb++) {
            int p = nb >> 1, s = nb & 1;
            mma16816(acc[mb][nb], f.ah[mb], f.bh[p][s], f.bh[p][s + 2]);
            mma16816(acc[mb][nb], f.ah[mb], f.bl[p][s], f.bl[p][s + 2]);
            mma16816(acc[mb][nb], f.al[mb], f.bh[p][s], f.bh[p][s + 2]);
        }
}

// ============================================================================
// G1: raw scores S = Q @ V^T. CTA tile 128(q) x 128(k), K=512 in 8 chunks.
// grid (kt=32, qt=32, b=4), 256 threads.
// ============================================================================
__global__ void __launch_bounds__(256) g1_scores(float* __restrict__ attn) {
    extern __shared__ char smem[];
    uint32_t sb0 = smem_to_u32(smem);
    uint32_t tb = (sb0 + 1023) & ~1023u;
    char* tbp = smem + (tb - sb0);
    int tid = threadIdx.x, wid = tid >> 5, lane = tid & 31;
    int mw = wid & 3, nw = wid >> 2;
    int kt = blockIdx.x, qt = blockIdx.y, b = blockIdx.z;

    const __half* pQh = g_Qh + ((size_t)(b * LSEQ + qt * 128)) * DDIM;
    const __half* pQl = g_Ql + ((size_t)(b * LSEQ + qt * 128)) * DDIM;
    const __half* pVh = g_Vh + ((size_t)(b * LSEQ + kt * 128)) * DDIM;
    const __half* pVl = g_Vl + ((size_t)(b * LSEQ + kt * 128)) * DDIM;

    float acc[2][8][4];
#pragma unroll
    for (int i = 0; i < 2; i++)
#pragma unroll
        for (int j = 0; j < 8; j++)
#pragma unroll
            for (int k = 0; k < 4; k++) acc[i][j][k] = 0.f;

    for (int c = 0; c < 8; c++) {
        __syncthreads();
        load_tile_h(tbp, OFF_AH, pQh, DDIM / 8, c, tid);
        load_tile_h(tbp, OFF_AL, pQl, DDIM / 8, c, tid);
        load_tile_h(tbp, OFF_BH, pVh, DDIM / 8, c, tid);
        load_tile_h(tbp, OFF_BL, pVl, DDIM / 8, c, tid);
        __syncthreads();
#pragma unroll
        for (int kk = 0; kk < 4; kk++) {
            Frag f;
            load_frags(f, tb + OFF_AH, tb + OFF_BH, mw, nw, kk, lane);
            mma_3prod(acc, f);
        }
    }

    // Epilogue: write raw scores
    int gid = lane >> 2, tig = lane & 3;
    size_t base = ((size_t)(b * LSEQ + qt * 128 + mw * 32)) * LSEQ
                + (size_t)kt * 128 + nw * 64;
#pragma unroll
    for (int mb = 0; mb < 2; mb++)
#pragma unroll
        for (int nb = 0; nb < 8; nb++) {
            size_t o0 = base + (size_t)(mb * 16 + gid) * LSEQ + nb * 8 + tig * 2;
            *reinterpret_cast<float2*>(&attn[o0]) =
                make_float2(acc[mb][nb][0], acc[mb][nb][1]);
            *reinterpret_cast<float2*>(&attn[o0 + 8 * LSEQ]) =
                make_float2(acc[mb][nb][2], acc[mb][nb][3]);
        }
}

// ============================================================================
// G2: per-row softmax in place. grid = 16384 rows, 256 threads.
// ============================================================================
__global__ void __launch_bounds__(256) g2_softmax(float* __restrict__ attn) {
    __shared__ float red[256];
    int tid = threadIdx.x;
    float* s = attn + (size_t)blockIdx.x * LSEQ;

    float m = -3.4e38f;
    for (int k = tid; k < LSEQ; k += 256) m = fmaxf(m, s[k]);
    red[tid] = m;
    __syncthreads();
    for (int off = 128; off; off >>= 1) {
        if (tid < off) red[tid] = fmaxf(red[tid], red[tid + off]);
        __syncthreads();
    }
    m = red[0];
    __syncthreads();

    float z = 0.f;
    for (int k = tid; k < LSEQ; k += 256) z += __expf(s[k] - m);
    red[tid] = z;
    __syncthreads();
    for (int off = 128; off; off >>= 1) {
        if (tid < off) red[tid] += red[tid + off];
        __syncthreads();
    }
    float iz = 1.0f / red[0];
    __syncthreads();

    for (int k = tid; k < LSEQ; k += 256) s[k] = __expf(s[k] - m) * iz;
}

// ============================================================================
// G3: context C = P @ V. CTA tile 128(q) x 128(d), K=4096 in 64 chunks.
// A = P hi/lo converted on the fly; B = VT hi/lo. grid (dt=4, qt=32, b=4).
// ============================================================================
__global__ void __launch_bounds__(256) g3_context(const float* __restrict__ attn,
                                                  float* __restrict__ ctx) {
    extern __shared__ char smem[];
    uint32_t sb0 = smem_to_u32(smem);
    uint32_t tb = (sb0 + 1023) & ~1023u;
    char* tbp = smem + (tb - sb0);
    int tid = threadIdx.x, wid = tid >> 5, lane = tid & 31;
    int mw = wid & 3, nw = wid >> 2;
    int dt = blockIdx.x, qt = blockIdx.y, b = blockIdx.z;

    size_t srow = ((size_t)(b * LSEQ + qt * 128)) * LSEQ;
    const __half* pBh = g_VTh + ((size_t)(b * DDIM + dt * 128)) * LSEQ;
    const __half* pBl = g_VTl + ((size_t)(b * DDIM + dt * 128)) * LSEQ;

    float acc[2][8][4];
#pragma unroll
    for (int i = 0; i < 2; i++)
#pragma unroll
        for (int j = 0; j < 8; j++)
#pragma unroll
            for (int k = 0; k < 4; k++) acc[i][j][k] = 0.f;

    for (int c = 0; c < 64; c++) {
        __syncthreads();
        // Convert P[128 x 64] fp32 -> fp16 hi/lo swizzled smem
#pragma unroll
        for (int it = 0; it < 8; it++) {
            int idx = tid + 256 * it;       // 0..2047 float4s
            int r = idx >> 4, s4 = idx & 15;
            float4 pv = *reinterpret_cast<const float4*>(
                &attn[srow + (size_t)r * LSEQ + c * 64 + s4 * 4]);
            __half h0 = __float2half_rn(pv.x), h1 = __float2half_rn(pv.y);
            __half h2 = __float2half_rn(pv.z), h3 = __float2half_rn(pv.w);
            __half l0 = __float2half_rn(pv.x - __half2float(h0));
            __half l1 = __float2half_rn(pv.y - __half2float(h1));
            __half l2 = __float2half_rn(pv.z - __half2float(h2));
            __half l3 = __float2half_rn(pv.w - __half2float(h3));
            uint32_t sw = sw128((uint32_t)(r * 128 + s4 * 8));
            *reinterpret_cast<__half2*>(tbp + OFF_AH + sw)     = __halves2half2(h0, h1);
            *reinterpret_cast<__half2*>(tbp + OFF_AH + sw + 4) = __halves2half2(h2, h3);
            *reinterpret_cast<__half2*>(tbp + OFF_AL + sw)     = __halves2half2(l0, l1);
            *reinterpret_cast<__half2*>(tbp + OFF_AL + sw + 4) = __halves2half2(l2, l3);
        }
        load_tile_h(tbp, OFF_BH, pBh, LSEQ / 8, c, tid);
        load_tile_h(tbp, OFF_BL, pBl, LSEQ / 8, c, tid);
        __syncthreads();
#pragma unroll
        for (int kk = 0; kk < 4; kk++) {
            Frag f;
            load_frags(f, tb + OFF_AH, tb + OFF_BH, mw, nw, kk, lane);
            mma_3prod(acc, f);
        }
    }

    // Epilogue: write context
    int gid = lane >> 2, tig = lane & 3;
    size_t base = ((size_t)(b * LSEQ + qt * 128 + mw * 32)) * DDIM
                + (size_t)dt * 128 + nw * 64;
#pragma unroll
    for (int mb = 0; mb < 2; mb++)
#pragma unroll
        for (int nb = 0; nb < 8; nb++) {
            size_t o0 = base + (size_t)(mb * 16 + gid) * DDIM + nb * 8 + tig * 2;
            *reinterpret_cast<float2*>(&ctx[o0]) =
                make_float2(acc[mb][nb][0], acc[mb][nb][1]);
            *reinterpret_cast<float2*>(&ctx[o0 + 8 * DDIM]) =
                make_float2(acc[mb][nb][2], acc[mb][nb][3]);
        }
}

// ============================================================================
// Launch
// ============================================================================
extern "C" void kernel_launch(void* const* d_in, const int* in_sizes, int n_in,
                              void* d_out, int out_size) {
    (void)in_sizes; (void)n_in; (void)out_size;
    const float* query = (const float*)d_in[0];
    const float* value = (const float*)d_in[1];
    float* out = (float*)d_out;
    float* ctx  = out;               // context first
    float* attn = out + CTX_ELEMS;   // then attn

    cudaFuncSetAttribute(g1_scores,  cudaFuncAttributeMaxDynamicSharedMemorySize, SMEM_DYN);
    cudaFuncSetAttribute(g3_context, cudaFuncAttributeMaxDynamicSharedMemorySize, SMEM_DYN);

    convert_qv<<<NELEM / 256, 256>>>(query, value);
    transpose_conv<<<dim3(LSEQ / 32, DDIM / 32, BATCH), dim3(32, 8)>>>(value);
    g1_scores<<<dim3(32, 32, 4), 256, SMEM_DYN>>>(attn);
    g2_softmax<<<BATCH * LSEQ, 256>>>(attn);
    g3_context<<<dim3(4, 32, 4), 256, SMEM_DYN>>>(attn, ctx);
}

// round 4
// speedup vs baseline: 1.4110x; 1.4110x over previous
#include <cuda_runtime.h>
#include <cuda_fp16.h>
#include <cstdint>

// ============================================================================
// Problem: B=4, Lq=Lk=4096, D=512, fp32. Output = (context, attn) concatenated.
// ============================================================================
#define BATCH 4
#define LSEQ  4096
#define DDIM  512
#define NELEM (BATCH * LSEQ * DDIM)              // 8,388,608
#define CTX_ELEMS ((size_t)BATCH * LSEQ * DDIM)

// fp16 hi/lo split scratch (device globals: sanctioned allocation-free scratch)
__device__ __align__(16) __half g_Qh[NELEM];
__device__ __align__(16) __half g_Ql[NELEM];
__device__ __align__(16) __half g_Vh[NELEM];
__device__ __align__(16) __half g_Vl[NELEM];
__device__ __align__(16) __half g_VTh[NELEM];  // [B, D, Lk]
__device__ __align__(16) __half g_VTl[NELEM];

// ============================================================================
// Helpers
// ============================================================================
__device__ __forceinline__ uint32_t smem_to_u32(const void* smem_ptr) {
    uint32_t addr;
    asm("{ .reg .u64 tmp; cvta.to.shared.u64 tmp, %1; cvt.u32.u64 %0, tmp; }"
        : "=r"(addr) : "l"(smem_ptr));
    return addr;
}

// ldmatrix x4 (non-transposed) from shared memory
__device__ __forceinline__ void ldsm_x4(uint32_t (&r)[4], uint32_t addr) {
    asm volatile("ldmatrix.sync.aligned.m8n8.x4.shared.b16 {%0,%1,%2,%3}, [%4];"
                 : "=r"(r[0]), "=r"(r[1]), "=r"(r[2]), "=r"(r[3]) : "r"(addr));
}

// mma m16n8k16 row.col fp16 x fp16 -> fp32 accumulate
__device__ __forceinline__ void mma16816(float (&d)[4], const uint32_t (&a)[4],
                                         uint32_t b0, uint32_t b1) {
    asm volatile(
        "mma.sync.aligned.m16n8k16.row.col.f32.f16.f16.f32 "
        "{%0,%1,%2,%3}, {%4,%5,%6,%7}, {%8,%9}, {%0,%1,%2,%3};"
        : "+f"(d[0]), "+f"(d[1]), "+f"(d[2]), "+f"(d[3])
        : "r"(a[0]), "r"(a[1]), "r"(a[2]), "r"(a[3]), "r"(b0), "r"(b1));
}

// SW128 swizzle for 128B rows
__device__ __forceinline__ uint32_t sw128(uint32_t off) {
    return off ^ ((off >> 3) & 0x70);
}

// G1 smem layout (3-product): 4 tiles of 128 x 64 halfs (16 KB each)
#define OFF_AH 0
#define OFF_AL 16384
#define OFF_BH 32768
#define OFF_BL 49152
#define SMEM_G1 (65536 + 1024)

// G3 smem layout (2-product): AH + BH + BL only
#define G3_AH 0
#define G3_BH 16384
#define G3_BL 32768
#define SMEM_G3 (49152 + 1024)

// ============================================================================
// P0a: elementwise convert Q,V -> fp16 hi/lo
// ============================================================================
__global__ void convert_qv(const float* __restrict__ Q, const float* __restrict__ V) {
    size_t i = (size_t)blockIdx.x * 256 + threadIdx.x;
    float q = Q[i];
    __half qh = __float2half_rn(q);
    g_Qh[i] = qh;
    g_Ql[i] = __float2half_rn(q - __half2float(qh));
    float v = V[i];
    __half vh = __float2half_rn(v);
    g_Vh[i] = vh;
    g_Vl[i] = __float2half_rn(v - __half2float(vh));
}

// ============================================================================
// P0b: transpose+convert V -> VT[b][d][k] fp16 hi/lo
// ============================================================================
__global__ void transpose_conv(const float* __restrict__ V) {
    __shared__ float tile[32][33];
    int b = blockIdx.z;
    int k0 = blockIdx.x * 32, d0 = blockIdx.y * 32;
    int tx = threadIdx.x, ty = threadIdx.y;  // 32 x 8
#pragma unroll
    for (int j = 0; j < 4; j++) {
        tile[ty + 8 * j][tx] =
            V[((size_t)b * LSEQ + k0 + ty + 8 * j) * DDIM + d0 + tx];
    }
    __syncthreads();
#pragma unroll
    for (int j = 0; j < 4; j++) {
        int d = d0 + ty + 8 * j, k = k0 + tx;
        float v = tile[tx][ty + 8 * j];
        size_t o = ((size_t)b * DDIM + d) * LSEQ + k;
        __half h = __float2half_rn(v);
        g_VTh[o] = h;
        g_VTl[o] = __float2half_rn(v - __half2float(h));
    }
}

// ============================================================================
// Tile loader: 128 rows x 64 halfs (16B vectors), SW128 swizzled, 256 threads
// ============================================================================
__device__ __forceinline__ void load_tile_h(char* tbp, int off,
                                            const __half* __restrict__ gsrc,
                                            int rowStrideU4, int chunk, int tid) {
    const uint4* g = reinterpret_cast<const uint4*>(gsrc);
#pragma unroll
    for (int it = 0; it < 4; it++) {
        int idx = tid + 256 * it;          // 0..1023
        int r = idx >> 3, s = idx & 7;
        uint4 val = g[(size_t)r * rowStrideU4 + (size_t)chunk * 8 + s];
        uint32_t sw = sw128((uint32_t)(r * 128 + s * 16));
        *reinterpret_cast<uint4*>(tbp + off + sw) = val;
    }
}

// ============================================================================
// G1 warp MMA core (3 products). Warp tile 32(m) x 64(n).
// ============================================================================
struct Frag {
    uint32_t ah[2][4], al[2][4];
    uint32_t bh[4][4], bl[4][4];
};

__device__ __forceinline__ void load_frags(Frag& f, uint32_t tA, uint32_t tB,
                                           int mw, int nw, int kk, int lane) {
    int kb = kk * 32 + ((lane >> 4) << 4);
#pragma unroll
    for (int mb = 0; mb < 2; mb++) {
        int row = mw * 32 + mb * 16 + (lane & 15);
        uint32_t addr = tA + row * 128 + (kb ^ ((row & 7) << 4));
        ldsm_x4(f.ah[mb], addr);
        ldsm_x4(f.al[mb], addr + 16384);
    }
#pragma unroll
    for (int p = 0; p < 4; p++) {
        int row = nw * 64 + p * 16 + ((lane >> 3 & 1) << 3) + (lane & 7);
        uint32_t addr = tB + row * 128 + (kb ^ ((row & 7) << 4));
        ldsm_x4(f.bh[p], addr);
        ldsm_x4(f.bl[p], addr + 16384);
    }
}

__device__ __forceinline__ void mma_3prod(float (&acc)[2][8][4], const Frag& f) {
#pragma unroll
    for (int mb = 0; mb < 2; mb++)
#pragma unroll
        for (int nb = 0; nb < 8; nb++) {
            int p = nb >> 1, s = nb & 1;
            mma16816(acc[mb][nb], f.ah[mb], f.bh[p][s], f.bh[p][s + 2]);
            mma16816(acc[mb][nb], f.ah[mb], f.bl[p][s], f.bl[p][s + 2]);
            mma16816(acc[mb][nb], f.al[mb], f.bh[p][s], f.bh[p][s + 2]);
        }
}

// ============================================================================
// G3 warp MMA core (2 products: A_hi x B_hi + A_hi x B_lo).
// ============================================================================
struct FragG3 {
    uint32_t ah[2][4];
    uint32_t bh[4][4], bl[4][4];
};

__device__ __forceinline__ void load_frags_g3(FragG3& f, uint32_t tA, uint32_t tB,
                                              int mw, int nw, int kk, int lane) {
    int kb = kk * 32 + ((lane >> 4) << 4);
#pragma unroll
    for (int mb = 0; mb < 2; mb++) {
        int row = mw * 32 + mb * 16 + (lane & 15);
        uint32_t addr = tA + row * 128 + (kb ^ ((row & 7) << 4));
        ldsm_x4(f.ah[mb], addr);
    }
#pragma unroll
    for (int p = 0; p < 4; p++) {
        int row = nw * 64 + p * 16 + ((lane >> 3 & 1) << 3) + (lane & 7);
        uint32_t addr = tB + row * 128 + (kb ^ ((row & 7) << 4));
        ldsm_x4(f.bh[p], addr);
        ldsm_x4(f.bl[p], addr + 16384);   // BL sits 16 KB above BH
    }
}

__device__ __forceinline__ void mma_2prod(float (&acc)[2][8][4], const FragG3& f) {
#pragma unroll
    for (int mb = 0; mb < 2; mb++)
#pragma unroll
        for (int nb = 0; nb < 8; nb++) {
            int p = nb >> 1, s = nb & 1;
            mma16816(acc[mb][nb], f.ah[mb], f.bh[p][s], f.bh[p][s + 2]);
            mma16816(acc[mb][nb], f.ah[mb], f.bl[p][s], f.bl[p][s + 2]);
        }
}

// ============================================================================
// G1: raw scores S = Q @ V^T. CTA tile 128(q) x 128(k), K=512 in 8 chunks.
// grid (kt=32, qt=32, b=4), 256 threads.
// ============================================================================
__global__ void __launch_bounds__(256) g1_scores(float* __restrict__ attn) {
    extern __shared__ char smem[];
    uint32_t sb0 = smem_to_u32(smem);
    uint32_t tb = (sb0 + 1023) & ~1023u;
    char* tbp = smem + (tb - sb0);
    int tid = threadIdx.x, wid = tid >> 5, lane = tid & 31;
    int mw = wid & 3, nw = wid >> 2;
    int kt = blockIdx.x, qt = blockIdx.y, b = blockIdx.z;

    const __half* pQh = g_Qh + ((size_t)(b * LSEQ + qt * 128)) * DDIM;
    const __half* pQl = g_Ql + ((size_t)(b * LSEQ + qt * 128)) * DDIM;
    const __half* pVh = g_Vh + ((size_t)(b * LSEQ + kt * 128)) * DDIM;
    const __half* pVl = g_Vl + ((size_t)(b * LSEQ + kt * 128)) * DDIM;

    float acc[2][8][4];
#pragma unroll
    for (int i = 0; i < 2; i++)
#pragma unroll
        for (int j = 0; j < 8; j++)
#pragma unroll
            for (int k = 0; k < 4; k++) acc[i][j][k] = 0.f;

    for (int c = 0; c < 8; c++) {
        __syncthreads();
        load_tile_h(tbp, OFF_AH, pQh, DDIM / 8, c, tid);
        load_tile_h(tbp, OFF_AL, pQl, DDIM / 8, c, tid);
        load_tile_h(tbp, OFF_BH, pVh, DDIM / 8, c, tid);
        load_tile_h(tbp, OFF_BL, pVl, DDIM / 8, c, tid);
        __syncthreads();
#pragma unroll
        for (int kk = 0; kk < 4; kk++) {
            Frag f;
            load_frags(f, tb + OFF_AH, tb + OFF_BH, mw, nw, kk, lane);
            mma_3prod(acc, f);
        }
    }

    // Epilogue: write raw scores
    int gid = lane >> 2, tig = lane & 3;
    size_t base = ((size_t)(b * LSEQ + qt * 128 + mw * 32)) * LSEQ
                + (size_t)kt * 128 + nw * 64;
#pragma unroll
    for (int mb = 0; mb < 2; mb++)
#pragma unroll
        for (int nb = 0; nb < 8; nb++) {
            size_t o0 = base + (size_t)(mb * 16 + gid) * LSEQ + nb * 8 + tig * 2;
            *reinterpret_cast<float2*>(&attn[o0]) =
                make_float2(acc[mb][nb][0], acc[mb][nb][1]);
            *reinterpret_cast<float2*>(&attn[o0 + 8 * LSEQ]) =
                make_float2(acc[mb][nb][2], acc[mb][nb][3]);
        }
}

// ============================================================================
// G2: single-pass register-resident row softmax. One block per row.
// 256 threads x 16 floats = 4096. One read + one write of the row.
// ============================================================================
__global__ void __launch_bounds__(256) g2_softmax(float* __restrict__ attn) {
    __shared__ float red[16];
    int tid = threadIdx.x, lane = tid & 31, w = tid >> 5;
    float4* row = reinterpret_cast<float4*>(attn + (size_t)blockIdx.x * LSEQ);

    float4 v[4];
#pragma unroll
    for (int i = 0; i < 4; i++) v[i] = row[tid + i * 256];

    float m = -3.4e38f;
#pragma unroll
    for (int i = 0; i < 4; i++)
        m = fmaxf(m, fmaxf(fmaxf(v[i].x, v[i].y), fmaxf(v[i].z, v[i].w)));
#pragma unroll
    for (int o = 16; o; o >>= 1) m = fmaxf(m, __shfl_xor_sync(~0u, m, o));
    if (lane == 0) red[w] = m;
    __syncthreads();
    m = red[0];
#pragma unroll
    for (int i = 1; i < 8; i++) m = fmaxf(m, red[i]);

    float z = 0.f;
#pragma unroll
    for (int i = 0; i < 4; i++) {
        v[i].x = __expf(v[i].x - m);
        v[i].y = __expf(v[i].y - m);
        v[i].z = __expf(v[i].z - m);
        v[i].w = __expf(v[i].w - m);
        z += (v[i].x + v[i].y) + (v[i].z + v[i].w);
    }
#pragma unroll
    for (int o = 16; o; o >>= 1) z += __shfl_xor_sync(~0u, z, o);
    if (lane == 0) red[8 + w] = z;
    __syncthreads();
    z = 0.f;
#pragma unroll
    for (int i = 0; i < 8; i++) z += red[8 + i];
    float iz = 1.0f / z;

#pragma unroll
    for (int i = 0; i < 4; i++) {
        v[i].x *= iz; v[i].y *= iz; v[i].z *= iz; v[i].w *= iz;
        row[tid + i * 256] = v[i];
    }
}

// ============================================================================
// G3: context C = P @ V. CTA tile 128(q) x 128(d), K=4096 in 64 chunks.
// 2-product: P_hi x (V_hi + V_lo). P_hi converted on the fly (no P_lo).
// grid (dt=4, qt=32, b=4).
// ============================================================================
__global__ void __launch_bounds__(256) g3_context(const float* __restrict__ attn,
                                                  float* __restrict__ ctx) {
    extern __shared__ char smem[];
    uint32_t sb0 = smem_to_u32(smem);
    uint32_t tb = (sb0 + 1023) & ~1023u;
    char* tbp = smem + (tb - sb0);
    int tid = threadIdx.x, wid = tid >> 5, lane = tid & 31;
    int mw = wid & 3, nw = wid >> 2;
    int dt = blockIdx.x, qt = blockIdx.y, b = blockIdx.z;

    size_t srow = ((size_t)(b * LSEQ + qt * 128)) * LSEQ;
    const __half* pBh = g_VTh + ((size_t)(b * DDIM + dt * 128)) * LSEQ;
    const __half* pBl = g_VTl + ((size_t)(b * DDIM + dt * 128)) * LSEQ;

    float acc[2][8][4];
#pragma unroll
    for (int i = 0; i < 2; i++)
#pragma unroll
        for (int j = 0; j < 8; j++)
#pragma unroll
            for (int k = 0; k < 4; k++) acc[i][j][k] = 0.f;

    for (int c = 0; c < 64; c++) {
        __syncthreads();
        // Convert P[128 x 64] fp32 -> fp16 hi only, swizzled smem
#pragma unroll
        for (int it = 0; it < 8; it++) {
            int idx = tid + 256 * it;       // 0..2047 float4s
            int r = idx >> 4, s4 = idx & 15;
            float4 pv = *reinterpret_cast<const float4*>(
                &attn[srow + (size_t)r * LSEQ + c * 64 + s4 * 4]);
            __half h0 = __float2half_rn(pv.x), h1 = __float2half_rn(pv.y);
            __half h2 = __float2half_rn(pv.z), h3 = __float2half_rn(pv.w);
            uint32_t sw = sw128((uint32_t)(r * 128 + s4 * 8));
            *reinterpret_cast<__half2*>(tbp + G3_AH + sw)     = __halves2half2(h0, h1);
            *reinterpret_cast<__half2*>(tbp + G3_AH + sw + 4) = __halves2half2(h2, h3);
        }
        load_tile_h(tbp, G3_BH, pBh, LSEQ / 8, c, tid);
        load_tile_h(tbp, G3_BL, pBl, LSEQ / 8, c, tid);
        __syncthreads();
#pragma unroll
        for (int kk = 0; kk < 4; kk++) {
            FragG3 f;
            load_frags_g3(f, tb + G3_AH, tb + G3_BH, mw, nw, kk, lane);
            mma_2prod(acc, f);
        }
    }

    // Epilogue: write context
    int gid = lane >> 2, tig = lane & 3;
    size_t base = ((size_t)(b * LSEQ + qt * 128 + mw * 32)) * DDIM
                + (size_t)dt * 128 + nw * 64;
#pragma unroll
    for (int mb = 0; mb < 2; mb++)
#pragma unroll
        for (int nb = 0; nb < 8; nb++) {
            size_t o0 = base + (size_t)(mb * 16 + gid) * DDIM + nb * 8 + tig * 2;
            *reinterpret_cast<float2*>(&ctx[o0]) =
                make_float2(acc[mb][nb][0], acc[mb][nb][1]);
            *reinterpret_cast<float2*>(&ctx[o0 + 8 * DDIM]) =
                make_float2(acc[mb][nb][2], acc[mb][nb][3]);
        }
}

// ============================================================================
// Launch
// ============================================================================
extern "C" void kernel_launch(void* const* d_in, const int* in_sizes, int n_in,
                              void* d_out, int out_size) {
    (void)in_sizes; (void)n_in; (void)out_size;
    const float* query = (const float*)d_in[0];
    const float* value = (const float*)d_in[1];
    float* out = (float*)d_out;
    float* ctx  = out;               // context first
    float* attn = out + CTX_ELEMS;   // then attn

    cudaFuncSetAttribute(g1_scores,  cudaFuncAttributeMaxDynamicSharedMemorySize, SMEM_G1);
    cudaFuncSetAttribute(g3_context, cudaFuncAttributeMaxDynamicSharedMemorySize, SMEM_G3);

    convert_qv<<<NELEM / 256, 256>>>(query, value);
    transpose_conv<<<dim3(LSEQ / 32, DDIM / 32, BATCH), dim3(32, 8)>>>(value);
    g1_scores<<<dim3(32, 32, 4), 256, SMEM_G1>>>(attn);
    g2_softmax<<<BATCH * LSEQ, 256>>>(attn);
    g3_context<<<dim3(4, 32, 4), 256, SMEM_G3>>>(attn, ctx);
}

// round 5
// speedup vs baseline: 1.5173x; 1.0753x over previous
#include <cuda_runtime.h>
#include <cuda_fp16.h>
#include <cstdint>

// ============================================================================
// Problem: B=4, Lq=Lk=4096, D=512, fp32. Output = (context, attn) concatenated.
// ============================================================================
#define BATCH 4
#define LSEQ  4096
#define DDIM  512
#define NELEM (BATCH * LSEQ * DDIM)              // 8,388,608
#define CTX_ELEMS ((size_t)BATCH * LSEQ * DDIM)
#define PELEMS ((size_t)BATCH * LSEQ * LSEQ)     // 67,108,864

// fp16 hi/lo split scratch (device globals: sanctioned allocation-free scratch)
__device__ __align__(16) __half g_Qh[NELEM];
__device__ __align__(16) __half g_Ql[NELEM];
__device__ __align__(16) __half g_Vh[NELEM];
__device__ __align__(16) __half g_Vl[NELEM];
__device__ __align__(16) __half g_VTh[NELEM];  // [B, D, Lk]
__device__ __align__(16) __half g_VTl[NELEM];
__device__ __align__(16) __half g_Ph[PELEMS];  // fp16 softmaxed P (written by G2)

// ============================================================================
// Helpers
// ============================================================================
__device__ __forceinline__ uint32_t smem_to_u32(const void* smem_ptr) {
    uint32_t addr;
    asm("{ .reg .u64 tmp; cvta.to.shared.u64 tmp, %1; cvt.u32.u64 %0, tmp; }"
        : "=r"(addr) : "l"(smem_ptr));
    return addr;
}

__device__ __forceinline__ void ldsm_x4(uint32_t (&r)[4], uint32_t addr) {
    asm volatile("ldmatrix.sync.aligned.m8n8.x4.shared.b16 {%0,%1,%2,%3}, [%4];"
                 : "=r"(r[0]), "=r"(r[1]), "=r"(r[2]), "=r"(r[3]) : "r"(addr));
}

__device__ __forceinline__ void mma16816(float (&d)[4], const uint32_t (&a)[4],
                                         uint32_t b0, uint32_t b1) {
    asm volatile(
        "mma.sync.aligned.m16n8k16.row.col.f32.f16.f16.f32 "
        "{%0,%1,%2,%3}, {%4,%5,%6,%7}, {%8,%9}, {%0,%1,%2,%3};"
        : "+f"(d[0]), "+f"(d[1]), "+f"(d[2]), "+f"(d[3])
        : "r"(a[0]), "r"(a[1]), "r"(a[2]), "r"(a[3]), "r"(b0), "r"(b1));
}

__device__ __forceinline__ uint32_t sw128(uint32_t off) {
    return off ^ ((off >> 3) & 0x70);
}

// cp.async 16B
__device__ __forceinline__ void cp16(uint32_t s, const void* g) {
    asm volatile("cp.async.cg.shared.global [%0], [%1], 16;" :: "r"(s), "l"(g));
}
#define CP_COMMIT() asm volatile("cp.async.commit_group;" ::: "memory")
#define CP_WAIT(n)  asm volatile("cp.async.wait_group %0;" :: "n"(n) : "memory")

// G1 smem layout (3-product): 4 tiles of 128 x 64 halfs (16 KB each)
#define OFF_AH 0
#define OFF_AL 16384
#define OFF_BH 32768
#define OFF_BL 49152
#define SMEM_G1 (65536 + 1024)

// G3 smem: 2 stages x (AH + BH + BL) = 2 x 48 KB
#define G3_STAGE 49152
#define SMEM_G3 (2 * G3_STAGE + 1024)

// ============================================================================
// P0a: elementwise convert Q,V -> fp16 hi/lo
// ============================================================================
__global__ void convert_qv(const float* __restrict__ Q, const float* __restrict__ V) {
    size_t i = (size_t)blockIdx.x * 256 + threadIdx.x;
    float q = Q[i];
    __half qh = __float2half_rn(q);
    g_Qh[i] = qh;
    g_Ql[i] = __float2half_rn(q - __half2float(qh));
    float v = V[i];
    __half vh = __float2half_rn(v);
    g_Vh[i] = vh;
    g_Vl[i] = __float2half_rn(v - __half2float(vh));
}

// ============================================================================
// P0b: transpose+convert V -> VT[b][d][k] fp16 hi/lo
// ============================================================================
__global__ void transpose_conv(const float* __restrict__ V) {
    __shared__ float tile[32][33];
    int b = blockIdx.z;
    int k0 = blockIdx.x * 32, d0 = blockIdx.y * 32;
    int tx = threadIdx.x, ty = threadIdx.y;  // 32 x 8
#pragma unroll
    for (int j = 0; j < 4; j++) {
        tile[ty + 8 * j][tx] =
            V[((size_t)b * LSEQ + k0 + ty + 8 * j) * DDIM + d0 + tx];
    }
    __syncthreads();
#pragma unroll
    for (int j = 0; j < 4; j++) {
        int d = d0 + ty + 8 * j, k = k0 + tx;
        float v = tile[tx][ty + 8 * j];
        size_t o = ((size_t)b * DDIM + d) * LSEQ + k;
        __half h = __float2half_rn(v);
        g_VTh[o] = h;
        g_VTl[o] = __float2half_rn(v - __half2float(h));
    }
}

// ============================================================================
// Tile loaders: 128 rows x 64 halfs (16B vectors), SW128 swizzled, 256 threads
// ============================================================================
__device__ __forceinline__ void load_tile_h(char* tbp, int off,
                                            const __half* __restrict__ gsrc,
                                            int rowStrideU4, int chunk, int tid) {
    const uint4* g = reinterpret_cast<const uint4*>(gsrc);
#pragma unroll
    for (int it = 0; it < 4; it++) {
        int idx = tid + 256 * it;
        int r = idx >> 3, s = idx & 7;
        uint4 val = g[(size_t)r * rowStrideU4 + (size_t)chunk * 8 + s];
        uint32_t sw = sw128((uint32_t)(r * 128 + s * 16));
        *reinterpret_cast<uint4*>(tbp + off + sw) = val;
    }
}

__device__ __forceinline__ void tile_cp(uint32_t sbase,
                                        const __half* __restrict__ gsrc,
                                        int rowStrideU4, int chunk, int tid) {
    const uint4* g = reinterpret_cast<const uint4*>(gsrc);
#pragma unroll
    for (int it = 0; it < 4; it++) {
        int idx = tid + 256 * it;
        int r = idx >> 3, s = idx & 7;
        cp16(sbase + sw128((uint32_t)(r * 128 + s * 16)),
             g + (size_t)r * rowStrideU4 + (size_t)chunk * 8 + s);
    }
}

// ============================================================================
// G1 warp MMA core (3 products). Warp tile 32(m) x 64(n).
// ============================================================================
struct Frag {
    uint32_t ah[2][4], al[2][4];
    uint32_t bh[4][4], bl[4][4];
};

__device__ __forceinline__ void load_frags(Frag& f, uint32_t tA, uint32_t tB,
                                           int mw, int nw, int kk, int lane) {
    int kb = kk * 32 + ((lane >> 4) << 4);
#pragma unroll
    for (int mb = 0; mb < 2; mb++) {
        int row = mw * 32 + mb * 16 + (lane & 15);
        uint32_t addr = tA + row * 128 + (kb ^ ((row & 7) << 4));
        ldsm_x4(f.ah[mb], addr);
        ldsm_x4(f.al[mb], addr + 16384);
    }
#pragma unroll
    for (int p = 0; p < 4; p++) {
        int row = nw * 64 + p * 16 + ((lane >> 3 & 1) << 3) + (lane & 7);
        uint32_t addr = tB + row * 128 + (kb ^ ((row & 7) << 4));
        ldsm_x4(f.bh[p], addr);
        ldsm_x4(f.bl[p], addr + 16384);
    }
}

__device__ __forceinline__ void mma_3prod(float (&acc)[2][8][4], const Frag& f) {
#pragma unroll
    for (int mb = 0; mb < 2; mb++)
#pragma unroll
        for (int nb = 0; nb < 8; nb++) {
            int p = nb >> 1, s = nb & 1;
            mma16816(acc[mb][nb], f.ah[mb], f.bh[p][s], f.bh[p][s + 2]);
            mma16816(acc[mb][nb], f.ah[mb], f.bl[p][s], f.bl[p][s + 2]);
            mma16816(acc[mb][nb], f.al[mb], f.bh[p][s], f.bh[p][s + 2]);
        }
}

// ============================================================================
// G3 warp MMA core (2 products: A_hi x B_hi + A_hi x B_lo).
// ============================================================================
struct FragG3 {
    uint32_t ah[2][4];
    uint32_t bh[4][4], bl[4][4];
};

__device__ __forceinline__ void load_frags_g3(FragG3& f, uint32_t tA, uint32_t tB,
                                              int mw, int nw, int kk, int lane) {
    int kb = kk * 32 + ((lane >> 4) << 4);
#pragma unroll
    for (int mb = 0; mb < 2; mb++) {
        int row = mw * 32 + mb * 16 + (lane & 15);
        uint32_t addr = tA + row * 128 + (kb ^ ((row & 7) << 4));
        ldsm_x4(f.ah[mb], addr);
    }
#pragma unroll
    for (int p = 0; p < 4; p++) {
        int row = nw * 64 + p * 16 + ((lane >> 3 & 1) << 3) + (lane & 7);
        uint32_t addr = tB + row * 128 + (kb ^ ((row & 7) << 4));
        ldsm_x4(f.bh[p], addr);
        ldsm_x4(f.bl[p], addr + 16384);   // BL sits 16 KB above BH
    }
}

__device__ __forceinline__ void mma_2prod(float (&acc)[2][8][4], const FragG3& f) {
#pragma unroll
    for (int mb = 0; mb < 2; mb++)
#pragma unroll
        for (int nb = 0; nb < 8; nb++) {
            int p = nb >> 1, s = nb & 1;
            mma16816(acc[mb][nb], f.ah[mb], f.bh[p][s], f.bh[p][s + 2]);
            mma16816(acc[mb][nb], f.ah[mb], f.bl[p][s], f.bl[p][s + 2]);
        }
}

// ============================================================================
// G1: raw scores S = Q @ V^T. CTA tile 128(q) x 128(k), K=512 in 8 chunks.
// grid (kt=32, qt=32, b=4), 256 threads.
// ============================================================================
__global__ void __launch_bounds__(256) g1_scores(float* __restrict__ attn) {
    extern __shared__ char smem[];
    uint32_t sb0 = smem_to_u32(smem);
    uint32_t tb = (sb0 + 1023) & ~1023u;
    char* tbp = smem + (tb - sb0);
    int tid = threadIdx.x, wid = tid >> 5, lane = tid & 31;
    int mw = wid & 3, nw = wid >> 2;
    int kt = blockIdx.x, qt = blockIdx.y, b = blockIdx.z;

    const __half* pQh = g_Qh + ((size_t)(b * LSEQ + qt * 128)) * DDIM;
    const __half* pQl = g_Ql + ((size_t)(b * LSEQ + qt * 128)) * DDIM;
    const __half* pVh = g_Vh + ((size_t)(b * LSEQ + kt * 128)) * DDIM;
    const __half* pVl = g_Vl + ((size_t)(b * LSEQ + kt * 128)) * DDIM;

    float acc[2][8][4];
#pragma unroll
    for (int i = 0; i < 2; i++)
#pragma unroll
        for (int j = 0; j < 8; j++)
#pragma unroll
            for (int k = 0; k < 4; k++) acc[i][j][k] = 0.f;

    for (int c = 0; c < 8; c++) {
        __syncthreads();
        load_tile_h(tbp, OFF_AH, pQh, DDIM / 8, c, tid);
        load_tile_h(tbp, OFF_AL, pQl, DDIM / 8, c, tid);
        load_tile_h(tbp, OFF_BH, pVh, DDIM / 8, c, tid);
        load_tile_h(tbp, OFF_BL, pVl, DDIM / 8, c, tid);
        __syncthreads();
#pragma unroll
        for (int kk = 0; kk < 4; kk++) {
            Frag f;
            load_frags(f, tb + OFF_AH, tb + OFF_BH, mw, nw, kk, lane);
            mma_3prod(acc, f);
        }
    }

    // Epilogue: write raw scores
    int gid = lane >> 2, tig = lane & 3;
    size_t base = ((size_t)(b * LSEQ + qt * 128 + mw * 32)) * LSEQ
                + (size_t)kt * 128 + nw * 64;
#pragma unroll
    for (int mb = 0; mb < 2; mb++)
#pragma unroll
        for (int nb = 0; nb < 8; nb++) {
            size_t o0 = base + (size_t)(mb * 16 + gid) * LSEQ + nb * 8 + tig * 2;
            *reinterpret_cast<float2*>(&attn[o0]) =
                make_float2(acc[mb][nb][0], acc[mb][nb][1]);
            *reinterpret_cast<float2*>(&attn[o0 + 8 * LSEQ]) =
                make_float2(acc[mb][nb][2], acc[mb][nb][3]);
        }
}

// ============================================================================
// G2: single-pass register-resident row softmax. One block per row.
// Writes fp32 p to attn AND fp16 p to g_Ph (feeds G3's A tiles).
// ============================================================================
__global__ void __launch_bounds__(256) g2_softmax(float* __restrict__ attn) {
    __shared__ float red[16];
    int tid = threadIdx.x, lane = tid & 31, w = tid >> 5;
    float4* row = reinterpret_cast<float4*>(attn + (size_t)blockIdx.x * LSEQ);
    __half2* hrow = reinterpret_cast<__half2*>(g_Ph + (size_t)blockIdx.x * LSEQ);

    float4 v[4];
#pragma unroll
    for (int i = 0; i < 4; i++) v[i] = row[tid + i * 256];

    float m = -3.4e38f;
#pragma unroll
    for (int i = 0; i < 4; i++)
        m = fmaxf(m, fmaxf(fmaxf(v[i].x, v[i].y), fmaxf(v[i].z, v[i].w)));
#pragma unroll
    for (int o = 16; o; o >>= 1) m = fmaxf(m, __shfl_xor_sync(~0u, m, o));
    if (lane == 0) red[w] = m;
    __syncthreads();
    m = red[0];
#pragma unroll
    for (int i = 1; i < 8; i++) m = fmaxf(m, red[i]);

    float z = 0.f;
#pragma unroll
    for (int i = 0; i < 4; i++) {
        v[i].x = __expf(v[i].x - m);
        v[i].y = __expf(v[i].y - m);
        v[i].z = __expf(v[i].z - m);
        v[i].w = __expf(v[i].w - m);
        z += (v[i].x + v[i].y) + (v[i].z + v[i].w);
    }
#pragma unroll
    for (int o = 16; o; o >>= 1) z += __shfl_xor_sync(~0u, z, o);
    if (lane == 0) red[8 + w] = z;
    __syncthreads();
    z = 0.f;
#pragma unroll
    for (int i = 0; i < 8; i++) z += red[8 + i];
    float iz = 1.0f / z;

#pragma unroll
    for (int i = 0; i < 4; i++) {
        v[i].x *= iz; v[i].y *= iz; v[i].z *= iz; v[i].w *= iz;
        row[tid + i * 256] = v[i];
        hrow[2 * (tid + i * 256)]     = __floats2half2_rn(v[i].x, v[i].y);
        hrow[2 * (tid + i * 256) + 1] = __floats2half2_rn(v[i].z, v[i].w);
    }
}

// ============================================================================
// G3: context C = P @ V. CTA tile 128(q) x 128(d), K=4096 in 64 chunks.
// 2-stage cp.async pipeline; A = g_Ph fp16 (no conversion); B = VT hi/lo.
// grid (dt=4, qt=32, b=4).
// ============================================================================
__global__ void __launch_bounds__(256) g3_context(float* __restrict__ ctx) {
    extern __shared__ char smem[];
    uint32_t sb0 = smem_to_u32(smem);
    uint32_t tb = (sb0 + 1023) & ~1023u;
    int tid = threadIdx.x, wid = tid >> 5, lane = tid & 31;
    int mw = wid & 3, nw = wid >> 2;
    int dt = blockIdx.x, qt = blockIdx.y, b = blockIdx.z;

    const __half* pA  = g_Ph  + ((size_t)(b * LSEQ + qt * 128)) * LSEQ;
    const __half* pBh = g_VTh + ((size_t)(b * DDIM + dt * 128)) * LSEQ;
    const __half* pBl = g_VTl + ((size_t)(b * DDIM + dt * 128)) * LSEQ;

    float acc[2][8][4];
#pragma unroll
    for (int i = 0; i < 2; i++)
#pragma unroll
        for (int j = 0; j < 8; j++)
#pragma unroll
            for (int k = 0; k < 4; k++) acc[i][j][k] = 0.f;

    // issue chunk c into stage s
    auto issue = [&](int c, int s) {
        uint32_t st = tb + s * G3_STAGE;
        tile_cp(st,         pA,  LSEQ / 8, c, tid);
        tile_cp(st + 16384, pBh, LSEQ / 8, c, tid);
        tile_cp(st + 32768, pBl, LSEQ / 8, c, tid);
        CP_COMMIT();
    };

    issue(0, 0);
    for (int c = 0; c < 64; c++) {
        if (c < 63) {
            issue(c + 1, (c + 1) & 1);
            CP_WAIT(1);
        } else {
            CP_WAIT(0);
        }
        __syncthreads();
        uint32_t st = tb + (c & 1) * G3_STAGE;
#pragma unroll
        for (int kk = 0; kk < 4; kk++) {
            FragG3 f;
            load_frags_g3(f, st, st + 16384, mw, nw, kk, lane);
            mma_2prod(acc, f);
        }
        __syncthreads();
    }

    // Epilogue: write context
    int gid = lane >> 2, tig = lane & 3;
    size_t base = ((size_t)(b * LSEQ + qt * 128 + mw * 32)) * DDIM
                + (size_t)dt * 128 + nw * 64;
#pragma unroll
    for (int mb = 0; mb < 2; mb++)
#pragma unroll
        for (int nb = 0; nb < 8; nb++) {
            size_t o0 = base + (size_t)(mb * 16 + gid) * DDIM + nb * 8 + tig * 2;
            *reinterpret_cast<float2*>(&ctx[o0]) =
                make_float2(acc[mb][nb][0], acc[mb][nb][1]);
            *reinterpret_cast<float2*>(&ctx[o0 + 8 * DDIM]) =
                make_float2(acc[mb][nb][2], acc[mb][nb][3]);
        }
}

// ============================================================================
// Launch
// ============================================================================
extern "C" void kernel_launch(void* const* d_in, const int* in_sizes, int n_in,
                              void* d_out, int out_size) {
    (void)in_sizes; (void)n_in; (void)out_size;
    const float* query = (const float*)d_in[0];
    const float* value = (const float*)d_in[1];
    float* out = (float*)d_out;
    float* ctx  = out;               // context first
    float* attn = out + CTX_ELEMS;   // then attn

    cudaFuncSetAttribute(g1_scores,  cudaFuncAttributeMaxDynamicSharedMemorySize, SMEM_G1);
    cudaFuncSetAttribute(g3_context, cudaFuncAttributeMaxDynamicSharedMemorySize, SMEM_G3);

    convert_qv<<<NELEM / 256, 256>>>(query, value);
    transpose_conv<<<dim3(LSEQ / 32, DDIM / 32, BATCH), dim3(32, 8)>>>(value);
    g1_scores<<<dim3(32, 32, 4), 256, SMEM_G1>>>(attn);
    g2_softmax<<<BATCH * LSEQ, 256>>>(attn);
    g3_context<<<dim3(4, 32, 4), 256, SMEM_G3>>>(ctx);
}

// round 6
// speedup vs baseline: 1.5429x; 1.0169x over previous
#include <cuda_runtime.h>
#include <cuda_fp16.h>
#include <cstdint>

// ============================================================================
// Problem: B=4, Lq=Lk=4096, D=512, fp32. Output = (context, attn) concatenated.
// ============================================================================
#define BATCH 4
#define LSEQ  4096
#define DDIM  512
#define NELEM (BATCH * LSEQ * DDIM)              // 8,388,608
#define CTX_ELEMS ((size_t)BATCH * LSEQ * DDIM)
#define PELEMS ((size_t)BATCH * LSEQ * LSEQ)     // 67,108,864

// fp16 hi/lo split scratch (device globals: sanctioned allocation-free scratch)
__device__ __align__(16) __half g_Qh[NELEM];
__device__ __align__(16) __half g_Ql[NELEM];
__device__ __align__(16) __half g_Vh[NELEM];
__device__ __align__(16) __half g_Vl[NELEM];
__device__ __align__(16) __half g_VTh[NELEM];  // [B, D, Lk]
__device__ __align__(16) __half g_VTl[NELEM];
__device__ __align__(16) __half g_Ph[PELEMS];  // fp16 softmaxed P (written by G2)

// ============================================================================
// Helpers
// ============================================================================
__device__ __forceinline__ uint32_t smem_to_u32(const void* smem_ptr) {
    uint32_t addr;
    asm("{ .reg .u64 tmp; cvta.to.shared.u64 tmp, %1; cvt.u32.u64 %0, tmp; }"
        : "=r"(addr) : "l"(smem_ptr));
    return addr;
}

__device__ __forceinline__ void ldsm_x4(uint32_t (&r)[4], uint32_t addr) {
    asm volatile("ldmatrix.sync.aligned.m8n8.x4.shared.b16 {%0,%1,%2,%3}, [%4];"
                 : "=r"(r[0]), "=r"(r[1]), "=r"(r[2]), "=r"(r[3]) : "r"(addr));
}

__device__ __forceinline__ void mma16816(float (&d)[4], const uint32_t (&a)[4],
                                         uint32_t b0, uint32_t b1) {
    asm volatile(
        "mma.sync.aligned.m16n8k16.row.col.f32.f16.f16.f32 "
        "{%0,%1,%2,%3}, {%4,%5,%6,%7}, {%8,%9}, {%0,%1,%2,%3};"
        : "+f"(d[0]), "+f"(d[1]), "+f"(d[2]), "+f"(d[3])
        : "r"(a[0]), "r"(a[1]), "r"(a[2]), "r"(a[3]), "r"(b0), "r"(b1));
}

__device__ __forceinline__ uint32_t sw128(uint32_t off) {
    return off ^ ((off >> 3) & 0x70);
}

// cp.async 16B
__device__ __forceinline__ void cp16(uint32_t s, const void* g) {
    asm volatile("cp.async.cg.shared.global [%0], [%1], 16;" :: "r"(s), "l"(g));
}
#define CP_COMMIT() asm volatile("cp.async.commit_group;" ::: "memory")
#define CP_WAIT(n)  asm volatile("cp.async.wait_group %0;" :: "n"(n) : "memory")

// G1 smem: 3 stages x (AH+AL+BH+BL = 64 KB)
#define G1_STAGE 65536
#define SMEM_G1 (3 * G1_STAGE + 1024)

// G3 smem: 2 stages x (AH + BH + BL) = 2 x 48 KB
#define G3_STAGE 49152
#define SMEM_G3 (2 * G3_STAGE + 1024)

// ============================================================================
// P0a: elementwise convert Q,V -> fp16 hi/lo
// ============================================================================
__global__ void convert_qv(const float* __restrict__ Q, const float* __restrict__ V) {
    size_t i = (size_t)blockIdx.x * 256 + threadIdx.x;
    float q = Q[i];
    __half qh = __float2half_rn(q);
    g_Qh[i] = qh;
    g_Ql[i] = __float2half_rn(q - __half2float(qh));
    float v = V[i];
    __half vh = __float2half_rn(v);
    g_Vh[i] = vh;
    g_Vl[i] = __float2half_rn(v - __half2float(vh));
}

// ============================================================================
// P0b: transpose+convert V -> VT[b][d][k] fp16 hi/lo
// ============================================================================
__global__ void transpose_conv(const float* __restrict__ V) {
    __shared__ float tile[32][33];
    int b = blockIdx.z;
    int k0 = blockIdx.x * 32, d0 = blockIdx.y * 32;
    int tx = threadIdx.x, ty = threadIdx.y;  // 32 x 8
#pragma unroll
    for (int j = 0; j < 4; j++) {
        tile[ty + 8 * j][tx] =
            V[((size_t)b * LSEQ + k0 + ty + 8 * j) * DDIM + d0 + tx];
    }
    __syncthreads();
#pragma unroll
    for (int j = 0; j < 4; j++) {
        int d = d0 + ty + 8 * j, k = k0 + tx;
        float v = tile[tx][ty + 8 * j];
        size_t o = ((size_t)b * DDIM + d) * LSEQ + k;
        __half h = __float2half_rn(v);
        g_VTh[o] = h;
        g_VTl[o] = __float2half_rn(v - __half2float(h));
    }
}

// ============================================================================
// cp.async tile loader: 128 rows x 64 halfs, SW128 swizzled, 256 threads
// ============================================================================
__device__ __forceinline__ void tile_cp(uint32_t sbase,
                                        const __half* __restrict__ gsrc,
                                        int rowStrideU4, int chunk, int tid) {
    const uint4* g = reinterpret_cast<const uint4*>(gsrc);
#pragma unroll
    for (int it = 0; it < 4; it++) {
        int idx = tid + 256 * it;
        int r = idx >> 3, s = idx & 7;
        cp16(sbase + sw128((uint32_t)(r * 128 + s * 16)),
             g + (size_t)r * rowStrideU4 + (size_t)chunk * 8 + s);
    }
}

// ============================================================================
// G1 warp MMA core (3 products). Warp tile 32(m) x 64(n).
// AL = AH + 16384, BL = BH + 16384 within a stage.
// ============================================================================
struct Frag {
    uint32_t ah[2][4], al[2][4];
    uint32_t bh[4][4], bl[4][4];
};

__device__ __forceinline__ void load_frags(Frag& f, uint32_t tA, uint32_t tB,
                                           int mw, int nw, int kk, int lane) {
    int kb = kk * 32 + ((lane >> 4) << 4);
#pragma unroll
    for (int mb = 0; mb < 2; mb++) {
        int row = mw * 32 + mb * 16 + (lane & 15);
        uint32_t addr = tA + row * 128 + (kb ^ ((row & 7) << 4));
        ldsm_x4(f.ah[mb], addr);
        ldsm_x4(f.al[mb], addr + 16384);
    }
#pragma unroll
    for (int p = 0; p < 4; p++) {
        int row = nw * 64 + p * 16 + ((lane >> 3 & 1) << 3) + (lane & 7);
        uint32_t addr = tB + row * 128 + (kb ^ ((row & 7) << 4));
        ldsm_x4(f.bh[p], addr);
        ldsm_x4(f.bl[p], addr + 16384);
    }
}

__device__ __forceinline__ void mma_3prod(float (&acc)[2][8][4], const Frag& f) {
#pragma unroll
    for (int mb = 0; mb < 2; mb++)
#pragma unroll
        for (int nb = 0; nb < 8; nb++) {
            int p = nb >> 1, s = nb & 1;
            mma16816(acc[mb][nb], f.ah[mb], f.bh[p][s], f.bh[p][s + 2]);
            mma16816(acc[mb][nb], f.ah[mb], f.bl[p][s], f.bl[p][s + 2]);
            mma16816(acc[mb][nb], f.al[mb], f.bh[p][s], f.bh[p][s + 2]);
        }
}

// ============================================================================
// G3 warp MMA core (2 products: A_hi x B_hi + A_hi x B_lo).
// ============================================================================
struct FragG3 {
    uint32_t ah[2][4];
    uint32_t bh[4][4], bl[4][4];
};

__device__ __forceinline__ void load_frags_g3(FragG3& f, uint32_t tA, uint32_t tB,
                                              int mw, int nw, int kk, int lane) {
    int kb = kk * 32 + ((lane >> 4) << 4);
#pragma unroll
    for (int mb = 0; mb < 2; mb++) {
        int row = mw * 32 + mb * 16 + (lane & 15);
        uint32_t addr = tA + row * 128 + (kb ^ ((row & 7) << 4));
        ldsm_x4(f.ah[mb], addr);
    }
#pragma unroll
    for (int p = 0; p < 4; p++) {
        int row = nw * 64 + p * 16 + ((lane >> 3 & 1) << 3) + (lane & 7);
        uint32_t addr = tB + row * 128 + (kb ^ ((row & 7) << 4));
        ldsm_x4(f.bh[p], addr);
        ldsm_x4(f.bl[p], addr + 16384);   // BL sits 16 KB above BH
    }
}

__device__ __forceinline__ void mma_2prod(float (&acc)[2][8][4], const FragG3& f) {
#pragma unroll
    for (int mb = 0; mb < 2; mb++)
#pragma unroll
        for (int nb = 0; nb < 8; nb++) {
            int p = nb >> 1, s = nb & 1;
            mma16816(acc[mb][nb], f.ah[mb], f.bh[p][s], f.bh[p][s + 2]);
            mma16816(acc[mb][nb], f.ah[mb], f.bl[p][s], f.bl[p][s + 2]);
        }
}

// ============================================================================
// G1: raw scores S = Q @ V^T. CTA tile 128(q) x 128(k), K=512 in 8 chunks.
// 3-stage cp.async pipeline (2 chunks ahead). grid (kt=32, qt=32, b=4), 256 thr.
// ============================================================================
__global__ void __launch_bounds__(256) g1_scores(float* __restrict__ attn) {
    extern __shared__ char smem[];
    uint32_t sb0 = smem_to_u32(smem);
    uint32_t tb = (sb0 + 1023) & ~1023u;
    int tid = threadIdx.x, wid = tid >> 5, lane = tid & 31;
    int mw = wid & 3, nw = wid >> 2;
    int kt = blockIdx.x, qt = blockIdx.y, b = blockIdx.z;

    const __half* pQh = g_Qh + ((size_t)(b * LSEQ + qt * 128)) * DDIM;
    const __half* pQl = g_Ql + ((size_t)(b * LSEQ + qt * 128)) * DDIM;
    const __half* pVh = g_Vh + ((size_t)(b * LSEQ + kt * 128)) * DDIM;
    const __half* pVl = g_Vl + ((size_t)(b * LSEQ + kt * 128)) * DDIM;

    float acc[2][8][4];
#pragma unroll
    for (int i = 0; i < 2; i++)
#pragma unroll
        for (int j = 0; j < 8; j++)
#pragma unroll
            for (int k = 0; k < 4; k++) acc[i][j][k] = 0.f;

    auto issue = [&](int c) {
        uint32_t st = tb + (uint32_t)(c % 3) * G1_STAGE;
        tile_cp(st,         pQh, DDIM / 8, c, tid);
        tile_cp(st + 16384, pQl, DDIM / 8, c, tid);
        tile_cp(st + 32768, pVh, DDIM / 8, c, tid);
        tile_cp(st + 49152, pVl, DDIM / 8, c, tid);
        CP_COMMIT();
    };

    issue(0);
    issue(1);
    for (int c = 0; c < 8; c++) {
        if (c < 6) {
            issue(c + 2);
            CP_WAIT(2);
        } else if (c == 6) {
            CP_WAIT(1);
        } else {
            CP_WAIT(0);
        }
        __syncthreads();
        uint32_t st = tb + (uint32_t)(c % 3) * G1_STAGE;
#pragma unroll
        for (int kk = 0; kk < 4; kk++) {
            Frag f;
            load_frags(f, st, st + 32768, mw, nw, kk, lane);
            mma_3prod(acc, f);
        }
        __syncthreads();   // all warps done reading stage before it is reused
    }

    // Epilogue: write raw scores
    int gid = lane >> 2, tig = lane & 3;
    size_t base = ((size_t)(b * LSEQ + qt * 128 + mw * 32)) * LSEQ
                + (size_t)kt * 128 + nw * 64;
#pragma unroll
    for (int mb = 0; mb < 2; mb++)
#pragma unroll
        for (int nb = 0; nb < 8; nb++) {
            size_t o0 = base + (size_t)(mb * 16 + gid) * LSEQ + nb * 8 + tig * 2;
            *reinterpret_cast<float2*>(&attn[o0]) =
                make_float2(acc[mb][nb][0], acc[mb][nb][1]);
            *reinterpret_cast<float2*>(&attn[o0 + 8 * LSEQ]) =
                make_float2(acc[mb][nb][2], acc[mb][nb][3]);
        }
}

// ============================================================================
// G2: single-pass register-resident row softmax. One block per row.
// Writes fp32 p to attn AND fp16 p to g_Ph (feeds G3's A tiles).
// ============================================================================
__global__ void __launch_bounds__(256) g2_softmax(float* __restrict__ attn) {
    __shared__ float red[16];
    int tid = threadIdx.x, lane = tid & 31, w = tid >> 5;
    float4* row = reinterpret_cast<float4*>(attn + (size_t)blockIdx.x * LSEQ);
    __half2* hrow = reinterpret_cast<__half2*>(g_Ph + (size_t)blockIdx.x * LSEQ);

    float4 v[4];
#pragma unroll
    for (int i = 0; i < 4; i++) v[i] = row[tid + i * 256];

    float m = -3.4e38f;
#pragma unroll
    for (int i = 0; i < 4; i++)
        m = fmaxf(m, fmaxf(fmaxf(v[i].x, v[i].y), fmaxf(v[i].z, v[i].w)));
#pragma unroll
    for (int o = 16; o; o >>= 1) m = fmaxf(m, __shfl_xor_sync(~0u, m, o));
    if (lane == 0) red[w] = m;
    __syncthreads();
    m = red[0];
#pragma unroll
    for (int i = 1; i < 8; i++) m = fmaxf(m, red[i]);

    float z = 0.f;
#pragma unroll
    for (int i = 0; i < 4; i++) {
        v[i].x = __expf(v[i].x - m);
        v[i].y = __expf(v[i].y - m);
        v[i].z = __expf(v[i].z - m);
        v[i].w = __expf(v[i].w - m);
        z += (v[i].x + v[i].y) + (v[i].z + v[i].w);
    }
#pragma unroll
    for (int o = 16; o; o >>= 1) z += __shfl_xor_sync(~0u, z, o);
    if (lane == 0) red[8 + w] = z;
    __syncthreads();
    z = 0.f;
#pragma unroll
    for (int i = 0; i < 8; i++) z += red[8 + i];
    float iz = 1.0f / z;

#pragma unroll
    for (int i = 0; i < 4; i++) {
        v[i].x *= iz; v[i].y *= iz; v[i].z *= iz; v[i].w *= iz;
        row[tid + i * 256] = v[i];
        hrow[2 * (tid + i * 256)]     = __floats2half2_rn(v[i].x, v[i].y);
        hrow[2 * (tid + i * 256) + 1] = __floats2half2_rn(v[i].z, v[i].w);
    }
}

// ============================================================================
// G3: context C = P @ V. CTA tile 128(q) x 128(d), K=4096 in 64 chunks.
// 2-stage cp.async pipeline; A = g_Ph fp16; B = VT hi/lo. grid (dt=4, qt=32, b=4).
// ============================================================================
__global__ void __launch_bounds__(256) g3_context(float* __restrict__ ctx) {
    extern __shared__ char smem[];
    uint32_t sb0 = smem_to_u32(smem);
    uint32_t tb = (sb0 + 1023) & ~1023u;
    int tid = threadIdx.x, wid = tid >> 5, lane = tid & 31;
    int mw = wid & 3, nw = wid >> 2;
    int dt = blockIdx.x, qt = blockIdx.y, b = blockIdx.z;

    const __half* pA  = g_Ph  + ((size_t)(b * LSEQ + qt * 128)) * LSEQ;
    const __half* pBh = g_VTh + ((size_t)(b * DDIM + dt * 128)) * LSEQ;
    const __half* pBl = g_VTl + ((size_t)(b * DDIM + dt * 128)) * LSEQ;

    float acc[2][8][4];
#pragma unroll
    for (int i = 0; i < 2; i++)
#pragma unroll
        for (int j = 0; j < 8; j++)
#pragma unroll
            for (int k = 0; k < 4; k++) acc[i][j][k] = 0.f;

    auto issue = [&](int c, int s) {
        uint32_t st = tb + s * G3_STAGE;
        tile_cp(st,         pA,  LSEQ / 8, c, tid);
        tile_cp(st + 16384, pBh, LSEQ / 8, c, tid);
        tile_cp(st + 32768, pBl, LSEQ / 8, c, tid);
        CP_COMMIT();
    };

    issue(0, 0);
    for (int c = 0; c < 64; c++) {
        if (c < 63) {
            issue(c + 1, (c + 1) & 1);
            CP_WAIT(1);
        } else {
            CP_WAIT(0);
        }
        __syncthreads();
        uint32_t st = tb + (c & 1) * G3_STAGE;
#pragma unroll
        for (int kk = 0; kk < 4; kk++) {
            FragG3 f;
            load_frags_g3(f, st, st + 16384, mw, nw, kk, lane);
            mma_2prod(acc, f);
        }
        __syncthreads();
    }

    // Epilogue: write context
    int gid = lane >> 2, tig = lane & 3;
    size_t base = ((size_t)(b * LSEQ + qt * 128 + mw * 32)) * DDIM
                + (size_t)dt * 128 + nw * 64;
#pragma unroll
    for (int mb = 0; mb < 2; mb++)
#pragma unroll
        for (int nb = 0; nb < 8; nb++) {
            size_t o0 = base + (size_t)(mb * 16 + gid) * DDIM + nb * 8 + tig * 2;
            *reinterpret_cast<float2*>(&ctx[o0]) =
                make_float2(acc[mb][nb][0], acc[mb][nb][1]);
            *reinterpret_cast<float2*>(&ctx[o0 + 8 * DDIM]) =
                make_float2(acc[mb][nb][2], acc[mb][nb][3]);
        }
}

// ============================================================================
// Launch
// ============================================================================
extern "C" void kernel_launch(void* const* d_in, const int* in_sizes, int n_in,
                              void* d_out, int out_size) {
    (void)in_sizes; (void)n_in; (void)out_size;
    const float* query = (const float*)d_in[0];
    const float* value = (const float*)d_in[1];
    float* out = (float*)d_out;
    float* ctx  = out;               // context first
    float* attn = out + CTX_ELEMS;   // then attn

    cudaFuncSetAttribute(g1_scores,  cudaFuncAttributeMaxDynamicSharedMemorySize, SMEM_G1);
    cudaFuncSetAttribute(g3_context, cudaFuncAttributeMaxDynamicSharedMemorySize, SMEM_G3);

    convert_qv<<<NELEM / 256, 256>>>(query, value);
    transpose_conv<<<dim3(LSEQ / 32, DDIM / 32, BATCH), dim3(32, 8)>>>(value);
    g1_scores<<<dim3(32, 32, 4), 256, SMEM_G1>>>(attn);
    g2_softmax<<<BATCH * LSEQ, 256>>>(attn);
    g3_context<<<dim3(4, 32, 4), 256, SMEM_G3>>>(ctx);
}

// round 7
// speedup vs baseline: 1.8444x; 1.1954x over previous
#include <cuda_runtime.h>
#include <cuda_fp16.h>
#include <cstdint>

// ============================================================================
// Problem: B=4, Lq=Lk=4096, D=512, fp32. Output = (context, attn) concatenated.
// ============================================================================
#define BATCH 4
#define LSEQ  4096
#define DDIM  512
#define NELEM (BATCH * LSEQ * DDIM)              // 8,388,608
#define CTX_ELEMS ((size_t)BATCH * LSEQ * DDIM)
#define PELEMS ((size_t)BATCH * LSEQ * LSEQ)     // 67,108,864

// fp16 hi/lo split scratch (device globals: sanctioned allocation-free scratch)
__device__ __align__(16) __half g_Qh[NELEM];
__device__ __align__(16) __half g_Ql[NELEM];
__device__ __align__(16) __half g_Vh[NELEM];
__device__ __align__(16) __half g_Vl[NELEM];
__device__ __align__(16) __half g_VTh[NELEM];  // [B, D, Lk] (hi only; G3 is 1-product)
__device__ __align__(16) __half g_Ph[PELEMS];  // fp16 softmaxed P (written by G2)

// ============================================================================
// Helpers
// ============================================================================
__device__ __forceinline__ uint32_t smem_to_u32(const void* smem_ptr) {
    uint32_t addr;
    asm("{ .reg .u64 tmp; cvta.to.shared.u64 tmp, %1; cvt.u32.u64 %0, tmp; }"
        : "=r"(addr) : "l"(smem_ptr));
    return addr;
}

__device__ __forceinline__ void ldsm_x4(uint32_t (&r)[4], uint32_t addr) {
    asm volatile("ldmatrix.sync.aligned.m8n8.x4.shared.b16 {%0,%1,%2,%3}, [%4];"
                 : "=r"(r[0]), "=r"(r[1]), "=r"(r[2]), "=r"(r[3]) : "r"(addr));
}

// fp32-accum HMMA
__device__ __forceinline__ void mma16816(float (&d)[4], const uint32_t (&a)[4],
                                         uint32_t b0, uint32_t b1) {
    asm volatile(
        "mma.sync.aligned.m16n8k16.row.col.f32.f16.f16.f32 "
        "{%0,%1,%2,%3}, {%4,%5,%6,%7}, {%8,%9}, {%0,%1,%2,%3};"
        : "+f"(d[0]), "+f"(d[1]), "+f"(d[2]), "+f"(d[3])
        : "r"(a[0]), "r"(a[1]), "r"(a[2]), "r"(a[3]), "r"(b0), "r"(b1));
}

// fp16-accum HMMA (for small correction products)
__device__ __forceinline__ void mma16816h(uint32_t (&d)[2], const uint32_t (&a)[4],
                                          uint32_t b0, uint32_t b1) {
    asm volatile(
        "mma.sync.aligned.m16n8k16.row.col.f16.f16.f16.f16 "
        "{%0,%1}, {%2,%3,%4,%5}, {%6,%7}, {%0,%1};"
        : "+r"(d[0]), "+r"(d[1])
        : "r"(a[0]), "r"(a[1]), "r"(a[2]), "r"(a[3]), "r"(b0), "r"(b1));
}

__device__ __forceinline__ uint32_t sw128(uint32_t off) {
    return off ^ ((off >> 3) & 0x70);
}

// cp.async 16B
__device__ __forceinline__ void cp16(uint32_t s, const void* g) {
    asm volatile("cp.async.cg.shared.global [%0], [%1], 16;" :: "r"(s), "l"(g));
}
#define CP_COMMIT() asm volatile("cp.async.commit_group;" ::: "memory")
#define CP_WAIT(n)  asm volatile("cp.async.wait_group %0;" :: "n"(n) : "memory")

// G1 smem: 3 stages x (AH+AL+BH+BL = 64 KB)
#define G1_STAGE 65536
#define SMEM_G1 (3 * G1_STAGE + 1024)

// G3 smem: 2 stages x (AH + BH) = 2 x 32 KB
#define G3_STAGE 32768
#define SMEM_G3 (2 * G3_STAGE + 1024)

// ============================================================================
// P0a: elementwise convert Q,V -> fp16 hi/lo
// ============================================================================
__global__ void convert_qv(const float* __restrict__ Q, const float* __restrict__ V) {
    size_t i = (size_t)blockIdx.x * 256 + threadIdx.x;
    float q = Q[i];
    __half qh = __float2half_rn(q);
    g_Qh[i] = qh;
    g_Ql[i] = __float2half_rn(q - __half2float(qh));
    float v = V[i];
    __half vh = __float2half_rn(v);
    g_Vh[i] = vh;
    g_Vl[i] = __float2half_rn(v - __half2float(vh));
}

// ============================================================================
// P0b: transpose+convert V -> VT[b][d][k] fp16 (hi only)
// ============================================================================
__global__ void transpose_conv(const float* __restrict__ V) {
    __shared__ float tile[32][33];
    int b = blockIdx.z;
    int k0 = blockIdx.x * 32, d0 = blockIdx.y * 32;
    int tx = threadIdx.x, ty = threadIdx.y;  // 32 x 8
#pragma unroll
    for (int j = 0; j < 4; j++) {
        tile[ty + 8 * j][tx] =
            V[((size_t)b * LSEQ + k0 + ty + 8 * j) * DDIM + d0 + tx];
    }
    __syncthreads();
#pragma unroll
    for (int j = 0; j < 4; j++) {
        int d = d0 + ty + 8 * j, k = k0 + tx;
        size_t o = ((size_t)b * DDIM + d) * LSEQ + k;
        g_VTh[o] = __float2half_rn(tile[tx][ty + 8 * j]);
    }
}

// ============================================================================
// cp.async tile loader: 128 rows x 64 halfs, SW128 swizzled, 256 threads
// ============================================================================
__device__ __forceinline__ void tile_cp(uint32_t sbase,
                                        const __half* __restrict__ gsrc,
                                        int rowStrideU4, int chunk, int tid) {
    const uint4* g = reinterpret_cast<const uint4*>(gsrc);
#pragma unroll
    for (int it = 0; it < 4; it++) {
        int idx = tid + 256 * it;
        int r = idx >> 3, s = idx & 7;
        cp16(sbase + sw128((uint32_t)(r * 128 + s * 16)),
             g + (size_t)r * rowStrideU4 + (size_t)chunk * 8 + s);
    }
}

// ============================================================================
// G1 warp MMA core. Warp tile 32(m) x 64(n). AL = AH+16384, BL = BH+16384.
// hh -> fp32 acc; hl + lh corrections -> fp16 acc.
// ============================================================================
struct Frag {
    uint32_t ah[2][4], al[2][4];
    uint32_t bh[4][4], bl[4][4];
};

__device__ __forceinline__ void load_frags(Frag& f, uint32_t tA, uint32_t tB,
                                           int mw, int nw, int kk, int lane) {
    int kb = kk * 32 + ((lane >> 4) << 4);
#pragma unroll
    for (int mb = 0; mb < 2; mb++) {
        int row = mw * 32 + mb * 16 + (lane & 15);
        uint32_t addr = tA + row * 128 + (kb ^ ((row & 7) << 4));
        ldsm_x4(f.ah[mb], addr);
        ldsm_x4(f.al[mb], addr + 16384);
    }
#pragma unroll
    for (int p = 0; p < 4; p++) {
        int row = nw * 64 + p * 16 + ((lane >> 3 & 1) << 3) + (lane & 7);
        uint32_t addr = tB + row * 128 + (kb ^ ((row & 7) << 4));
        ldsm_x4(f.bh[p], addr);
        ldsm_x4(f.bl[p], addr + 16384);
    }
}

__device__ __forceinline__ void mma_g1(float (&accf)[2][8][4],
                                       uint32_t (&acch)[2][8][2], const Frag& f) {
#pragma unroll
    for (int mb = 0; mb < 2; mb++)
#pragma unroll
        for (int nb = 0; nb < 8; nb++) {
            int p = nb >> 1, s = nb & 1;
            mma16816(accf[mb][nb], f.ah[mb], f.bh[p][s], f.bh[p][s + 2]);
            mma16816h(acch[mb][nb], f.ah[mb], f.bl[p][s], f.bl[p][s + 2]);
            mma16816h(acch[mb][nb], f.al[mb], f.bh[p][s], f.bh[p][s + 2]);
        }
}

// ============================================================================
// G3 warp MMA core (single product: P_h x V_h).
// ============================================================================
struct FragG3 {
    uint32_t ah[2][4];
    uint32_t bh[4][4];
};

__device__ __forceinline__ void load_frags_g3(FragG3& f, uint32_t tA, uint32_t tB,
                                              int mw, int nw, int kk, int lane) {
    int kb = kk * 32 + ((lane >> 4) << 4);
#pragma unroll
    for (int mb = 0; mb < 2; mb++) {
        int row = mw * 32 + mb * 16 + (lane & 15);
        ldsm_x4(f.ah[mb], tA + row * 128 + (kb ^ ((row & 7) << 4)));
    }
#pragma unroll
    for (int p = 0; p < 4; p++) {
        int row = nw * 64 + p * 16 + ((lane >> 3 & 1) << 3) + (lane & 7);
        ldsm_x4(f.bh[p], tB + row * 128 + (kb ^ ((row & 7) << 4)));
    }
}

__device__ __forceinline__ void mma_1prod(float (&acc)[2][8][4], const FragG3& f) {
#pragma unroll
    for (int mb = 0; mb < 2; mb++)
#pragma unroll
        for (int nb = 0; nb < 8; nb++) {
            int p = nb >> 1, s = nb & 1;
            mma16816(acc[mb][nb], f.ah[mb], f.bh[p][s], f.bh[p][s + 2]);
        }
}

// ============================================================================
// G1: raw scores S = Q @ V^T. CTA tile 128(q) x 128(k), K=512 in 8 chunks.
// 3-stage cp.async pipeline. grid (kt=32, qt=32, b=4), 256 threads.
// ============================================================================
__global__ void __launch_bounds__(256) g1_scores(float* __restrict__ attn) {
    extern __shared__ char smem[];
    uint32_t sb0 = smem_to_u32(smem);
    uint32_t tb = (sb0 + 1023) & ~1023u;
    int tid = threadIdx.x, wid = tid >> 5, lane = tid & 31;
    int mw = wid & 3, nw = wid >> 2;
    int kt = blockIdx.x, qt = blockIdx.y, b = blockIdx.z;

    const __half* pQh = g_Qh + ((size_t)(b * LSEQ + qt * 128)) * DDIM;
    const __half* pQl = g_Ql + ((size_t)(b * LSEQ + qt * 128)) * DDIM;
    const __half* pVh = g_Vh + ((size_t)(b * LSEQ + kt * 128)) * DDIM;
    const __half* pVl = g_Vl + ((size_t)(b * LSEQ + kt * 128)) * DDIM;

    float accf[2][8][4];
    uint32_t acch[2][8][2];
#pragma unroll
    for (int i = 0; i < 2; i++)
#pragma unroll
        for (int j = 0; j < 8; j++) {
#pragma unroll
            for (int k = 0; k < 4; k++) accf[i][j][k] = 0.f;
            acch[i][j][0] = 0u;
            acch[i][j][1] = 0u;
        }

    auto issue = [&](int c) {
        uint32_t st = tb + (uint32_t)(c % 3) * G1_STAGE;
        tile_cp(st,         pQh, DDIM / 8, c, tid);
        tile_cp(st + 16384, pQl, DDIM / 8, c, tid);
        tile_cp(st + 32768, pVh, DDIM / 8, c, tid);
        tile_cp(st + 49152, pVl, DDIM / 8, c, tid);
        CP_COMMIT();
    };

    issue(0);
    issue(1);
    for (int c = 0; c < 8; c++) {
        if (c < 6) {
            issue(c + 2);
            CP_WAIT(2);
        } else if (c == 6) {
            CP_WAIT(1);
        } else {
            CP_WAIT(0);
        }
        __syncthreads();
        uint32_t st = tb + (uint32_t)(c % 3) * G1_STAGE;
#pragma unroll
        for (int kk = 0; kk < 4; kk++) {
            Frag f;
            load_frags(f, st, st + 32768, mw, nw, kk, lane);
            mma_g1(accf, acch, f);
        }
        __syncthreads();
    }

    // Epilogue: merge fp16 corrections into fp32 and write raw scores
    int gid = lane >> 2, tig = lane & 3;
    size_t base = ((size_t)(b * LSEQ + qt * 128 + mw * 32)) * LSEQ
                + (size_t)kt * 128 + nw * 64;
#pragma unroll
    for (int mb = 0; mb < 2; mb++)
#pragma unroll
        for (int nb = 0; nb < 8; nb++) {
            float2 c01 = __half22float2(*reinterpret_cast<const __half2*>(&acch[mb][nb][0]));
            float2 c23 = __half22float2(*reinterpret_cast<const __half2*>(&acch[mb][nb][1]));
            size_t o0 = base + (size_t)(mb * 16 + gid) * LSEQ + nb * 8 + tig * 2;
            *reinterpret_cast<float2*>(&attn[o0]) =
                make_float2(accf[mb][nb][0] + c01.x, accf[mb][nb][1] + c01.y);
            *reinterpret_cast<float2*>(&attn[o0 + 8 * LSEQ]) =
                make_float2(accf[mb][nb][2] + c23.x, accf[mb][nb][3] + c23.y);
        }
}

// ============================================================================
// G2: single-pass register-resident row softmax. One block per row.
// Writes fp32 p to attn AND fp16 p to g_Ph (feeds G3's A tiles).
// ============================================================================
__global__ void __launch_bounds__(256) g2_softmax(float* __restrict__ attn) {
    __shared__ float red[16];
    int tid = threadIdx.x, lane = tid & 31, w = tid >> 5;
    float4* row = reinterpret_cast<float4*>(attn + (size_t)blockIdx.x * LSEQ);
    __half2* hrow = reinterpret_cast<__half2*>(g_Ph + (size_t)blockIdx.x * LSEQ);

    float4 v[4];
#pragma unroll
    for (int i = 0; i < 4; i++) v[i] = row[tid + i * 256];

    float m = -3.4e38f;
#pragma unroll
    for (int i = 0; i < 4; i++)
        m = fmaxf(m, fmaxf(fmaxf(v[i].x, v[i].y), fmaxf(v[i].z, v[i].w)));
#pragma unroll
    for (int o = 16; o; o >>= 1) m = fmaxf(m, __shfl_xor_sync(~0u, m, o));
    if (lane == 0) red[w] = m;
    __syncthreads();
    m = red[0];
#pragma unroll
    for (int i = 1; i < 8; i++) m = fmaxf(m, red[i]);

    float z = 0.f;
#pragma unroll
    for (int i = 0; i < 4; i++) {
        v[i].x = __expf(v[i].x - m);
        v[i].y = __expf(v[i].y - m);
        v[i].z = __expf(v[i].z - m);
        v[i].w = __expf(v[i].w - m);
        z += (v[i].x + v[i].y) + (v[i].z + v[i].w);
    }
#pragma unroll
    for (int o = 16; o; o >>= 1) z += __shfl_xor_sync(~0u, z, o);
    if (lane == 0) red[8 + w] = z;
    __syncthreads();
    z = 0.f;
#pragma unroll
    for (int i = 0; i < 8; i++) z += red[8 + i];
    float iz = 1.0f / z;

#pragma unroll
    for (int i = 0; i < 4; i++) {
        v[i].x *= iz; v[i].y *= iz; v[i].z *= iz; v[i].w *= iz;
        row[tid + i * 256] = v[i];
        hrow[2 * (tid + i * 256)]     = __floats2half2_rn(v[i].x, v[i].y);
        hrow[2 * (tid + i * 256) + 1] = __floats2half2_rn(v[i].z, v[i].w);
    }
}

// ============================================================================
// G3: context C = P @ V. CTA tile 128(q) x 128(d), K=4096 in 64 chunks.
// Single-product (P_h x V_h), 2-stage cp.async. grid (dt=4, qt=32, b=4).
// ============================================================================
__global__ void __launch_bounds__(256) g3_context(float* __restrict__ ctx) {
    extern __shared__ char smem[];
    uint32_t sb0 = smem_to_u32(smem);
    uint32_t tb = (sb0 + 1023) & ~1023u;
    int tid = threadIdx.x, wid = tid >> 5, lane = tid & 31;
    int mw = wid & 3, nw = wid >> 2;
    int dt = blockIdx.x, qt = blockIdx.y, b = blockIdx.z;

    const __half* pA  = g_Ph  + ((size_t)(b * LSEQ + qt * 128)) * LSEQ;
    const __half* pBh = g_VTh + ((size_t)(b * DDIM + dt * 128)) * LSEQ;

    float acc[2][8][4];
#pragma unroll
    for (int i = 0; i < 2; i++)
#pragma unroll
        for (int j = 0; j < 8; j++)
#pragma unroll
            for (int k = 0; k < 4; k++) acc[i][j][k] = 0.f;

    auto issue = [&](int c, int s) {
        uint32_t st = tb + s * G3_STAGE;
        tile_cp(st,         pA,  LSEQ / 8, c, tid);
        tile_cp(st + 16384, pBh, LSEQ / 8, c, tid);
        CP_COMMIT();
    };

    issue(0, 0);
    for (int c = 0; c < 64; c++) {
        if (c < 63) {
            issue(c + 1, (c + 1) & 1);
            CP_WAIT(1);
        } else {
            CP_WAIT(0);
        }
        __syncthreads();
        uint32_t st = tb + (c & 1) * G3_STAGE;
#pragma unroll
        for (int kk = 0; kk < 4; kk++) {
            FragG3 f;
            load_frags_g3(f, st, st + 16384, mw, nw, kk, lane);
            mma_1prod(acc, f);
        }
        __syncthreads();
    }

    // Epilogue: write context
    int gid = lane >> 2, tig = lane & 3;
    size_t base = ((size_t)(b * LSEQ + qt * 128 + mw * 32)) * DDIM
                + (size_t)dt * 128 + nw * 64;
#pragma unroll
    for (int mb = 0; mb < 2; mb++)
#pragma unroll
        for (int nb = 0; nb < 8; nb++) {
            size_t o0 = base + (size_t)(mb * 16 + gid) * DDIM + nb * 8 + tig * 2;
            *reinterpret_cast<float2*>(&ctx[o0]) =
                make_float2(acc[mb][nb][0], acc[mb][nb][1]);
            *reinterpret_cast<float2*>(&ctx[o0 + 8 * DDIM]) =
                make_float2(acc[mb][nb][2], acc[mb][nb][3]);
        }
}

// ============================================================================
// Launch
// ============================================================================
extern "C" void kernel_launch(void* const* d_in, const int* in_sizes, int n_in,
                              void* d_out, int out_size) {
    (void)in_sizes; (void)n_in; (void)out_size;
    const float* query = (const float*)d_in[0];
    const float* value = (const float*)d_in[1];
    float* out = (float*)d_out;
    float* ctx  = out;               // context first
    float* attn = out + CTX_ELEMS;   // then attn

    cudaFuncSetAttribute(g1_scores,  cudaFuncAttributeMaxDynamicSharedMemorySize, SMEM_G1);
    cudaFuncSetAttribute(g3_context, cudaFuncAttributeMaxDynamicSharedMemorySize, SMEM_G3);

    convert_qv<<<NELEM / 256, 256>>>(query, value);
    transpose_conv<<<dim3(LSEQ / 32, DDIM / 32, BATCH), dim3(32, 8)>>>(value);
    g1_scores<<<dim3(32, 32, 4), 256, SMEM_G1>>>(attn);
    g2_softmax<<<BATCH * LSEQ, 256>>>(attn);
    g3_context<<<dim3(4, 32, 4), 256, SMEM_G3>>>(ctx);
}